// round 14
// baseline (speedup 1.0000x reference)
#include <cuda_runtime.h>
#include <cuda_bf16.h>
#include <cuda_fp16.h>
#include <math.h>
#include <stdint.h>

// ---------------- problem constants ----------------
#define NN      50000
#define NE      800000
#define IN_DIM  256
#define H1N     4
#define D1N     128
#define C1N     512
#define H2N     1
#define D2N     256
#define C2N     256
#define NEG_SLOPE 0.2f

#define SCAN_BS 1024
#define SCAN_NB ((NN + SCAN_BS - 1) / SCAN_BS)

// ---------------- device scratch ----------------
__device__ float                         g_h1 [(size_t)NN * C1N];
__device__ __align__(16) __half          g_h1f16[(size_t)NN * C1N];
__device__ float                         g_h2 [(size_t)NN * C2N];
__device__ __align__(16) __nv_bfloat16   g_a1hi[(size_t)NN * IN_DIM];
__device__ __align__(16) __nv_bfloat16   g_a1lo[(size_t)NN * IN_DIM];
__device__ __align__(16) __nv_bfloat16   g_a2hi[(size_t)NN * C1N];
__device__ __align__(16) __nv_bfloat16   g_a2lo[(size_t)NN * C1N];
__device__ __align__(16) __nv_bfloat16   g_w1thi[(size_t)C1N * IN_DIM];
__device__ __align__(16) __nv_bfloat16   g_w1tlo[(size_t)C1N * IN_DIM];
__device__ __align__(16) __nv_bfloat16   g_w2thi[(size_t)C2N * C1N];
__device__ __align__(16) __nv_bfloat16   g_w2tlo[(size_t)C2N * C1N];
__device__ float                         g_el1[(size_t)NN * H1N];
__device__ float                         g_er1[(size_t)NN * H1N];
__device__ float                         g_el2[(size_t)NN * H2N];
__device__ float                         g_er2[(size_t)NN * H2N];
// merged CSR scratch (layer-major)
__device__ int   g_cnt[2 * NN];
__device__ int   g_part[2 * NN];
__device__ int   g_bsum[128];
__device__ int   g_soff[128];
__device__ int   g_cursor[2 * NN];
__device__ int   g_rowptr1[NN + 1];
__device__ int   g_rowptr2[NN + 1];
__device__ int   g_csrc1[NE];
__device__ int   g_csrc2[NE];

// ---------------- bf16 split helpers ----------------
__device__ __forceinline__ unsigned pk(__nv_bfloat16 a, __nv_bfloat16 b) {
    __nv_bfloat162 t = __halves2bfloat162(a, b);
    return *reinterpret_cast<unsigned*>(&t);
}
__device__ __forceinline__ void split1(float x, __nv_bfloat16& h, __nv_bfloat16& l) {
    h = __float2bfloat16(x);
    l = __float2bfloat16(x - __bfloat162float(h));
}

// ---------------- prep kernels ----------------
__global__ void split_kernel(const float4* __restrict__ x,
                             uint2* __restrict__ hi, uint2* __restrict__ lo, int n4) {
    int stride = gridDim.x * blockDim.x;
    for (int i = blockIdx.x * blockDim.x + threadIdx.x; i < n4; i += stride) {
        float4 v = x[i];
        __nv_bfloat16 hx, hy, hz, hw, lx, ly, lz, lw;
        split1(v.x, hx, lx); split1(v.y, hy, ly);
        split1(v.z, hz, lz); split1(v.w, hw, lw);
        uint2 H, L;
        H.x = pk(hx, hy); H.y = pk(hz, hw);
        L.x = pk(lx, ly); L.y = pk(lz, lw);
        hi[i] = H; lo[i] = L;
    }
}

__global__ void tsplit_kernel(const float* __restrict__ W,
                              __nv_bfloat16* __restrict__ thi,
                              __nv_bfloat16* __restrict__ tlo, int K, int Ncol) {
    int idx = blockIdx.x * blockDim.x + threadIdx.x;
    if (idx >= K * Ncol) return;
    int n = idx / K, k = idx - n * K;
    float x = W[(size_t)k * Ncol + n];
    __nv_bfloat16 h, l;
    split1(x, h, l);
    thi[idx] = h; tlo[idx] = l;
}

// ---------------- mma.sync bf16x3 GEMM (proven R10 config + optional fp16 copy) ----------------
#define MMA_BF16(D, A, B)                                                        \
    asm volatile("mma.sync.aligned.m16n8k16.row.col.f32.bf16.bf16.f32 "          \
                 "{%0,%1,%2,%3},{%4,%5,%6,%7},{%8,%9},{%0,%1,%2,%3};"            \
                 : "+f"((D)[0]), "+f"((D)[1]), "+f"((D)[2]), "+f"((D)[3])        \
                 : "r"((A)[0]), "r"((A)[1]), "r"((A)[2]), "r"((A)[3]),           \
                   "r"((B)[0]), "r"((B)[1]))

#define LDSM4(R0, R1, R2, R3, ADDR)                                              \
    asm volatile("ldmatrix.sync.aligned.m8n8.x4.shared.b16 {%0,%1,%2,%3}, [%4];" \
                 : "=r"(R0), "=r"(R1), "=r"(R2), "=r"(R3) : "r"(ADDR))

__device__ __forceinline__ void cp16(uint32_t saddr, const void* gaddr, bool pred) {
    int sz = pred ? 16 : 0;
    asm volatile("cp.async.cg.shared.global [%0], [%1], 16, %2;"
                 :: "r"(saddr), "l"(gaddr), "r"(sz));
}
#define CP_COMMIT() asm volatile("cp.async.commit_group;")
template<int N>
__device__ __forceinline__ void cp_wait() {
    asm volatile("cp.async.wait_group %0;" :: "n"(N));
}

__device__ __forceinline__ uint32_t swz(int r, int c) {
    return (uint32_t)((r * 4 + (c ^ (r & 3))) << 4);
}

#define STG_A_H 0
#define STG_A_L 8192
#define STG_B_H 16384
#define STG_B_L 20480
#define STG_SZ  24576

__global__ __launch_bounds__(256, 3)
void mma_bf16x3_kernel(int M, int Ncol, int K,
                       const __nv_bfloat16* __restrict__ Ahi,
                       const __nv_bfloat16* __restrict__ Alo,
                       const __nv_bfloat16* __restrict__ Bthi,
                       const __nv_bfloat16* __restrict__ Btlo,
                       float* __restrict__ C,
                       __half* __restrict__ C16) {
    __shared__ char smem[2 * STG_SZ];
    const int tid  = threadIdx.x;
    const int lane = tid & 31;
    const int wid  = tid >> 5;
    const int warp_m = wid & 3;
    const int warp_n = wid >> 2;
    const int mBase = blockIdx.y * 128;
    const int nBase = blockIdx.x * 64;
    const uint32_t sb = (uint32_t)__cvta_generic_to_shared(smem);

    float acc[2][4][4];
#pragma unroll
    for (int i = 0; i < 2; i++)
#pragma unroll
        for (int j = 0; j < 4; j++)
#pragma unroll
            for (int c = 0; c < 4; c++) acc[i][j][c] = 0.f;

    const int ar = tid >> 2;
    const int ac = tid & 3;
    const uint32_t soA0 = swz(ar, ac);
    const uint32_t soA1 = swz(ar + 64, ac);

    const int nk = K >> 5;

    auto load_stage = [&](int kb, int s) {
        const uint32_t st = sb + (uint32_t)s * STG_SZ;
        const int kOff = kb * 32 + ac * 8;
        {
            bool p0 = (mBase + ar) < M;
            bool p1 = (mBase + ar + 64) < M;
            size_t o0 = (size_t)(mBase + ar) * K + kOff;
            size_t o1 = (size_t)(mBase + ar + 64) * K + kOff;
            cp16(st + STG_A_H + soA0, Ahi + o0, p0);
            cp16(st + STG_A_H + soA1, Ahi + o1, p1);
            cp16(st + STG_A_L + soA0, Alo + o0, p0);
            cp16(st + STG_A_L + soA1, Alo + o1, p1);
        }
        {
            size_t ob = (size_t)(nBase + ar) * K + kOff;
            cp16(st + STG_B_H + soA0, Bthi + ob, true);
            cp16(st + STG_B_L + soA0, Btlo + ob, true);
        }
        CP_COMMIT();
    };

    load_stage(0, 0);

    for (int kb = 0; kb < nk; kb++) {
        if (kb + 1 < nk) load_stage(kb + 1, (kb + 1) & 1);
        if (kb + 1 < nk) cp_wait<1>(); else cp_wait<0>();
        __syncthreads();

        const uint32_t st = sb + (uint32_t)(kb & 1) * STG_SZ;
#pragma unroll
        for (int ks = 0; ks < 2; ks++) {
            const int c0 = ks * 2 + (lane >> 4);
            uint32_t ah[2][4], al[2][4];
#pragma unroll
            for (int i = 0; i < 2; i++) {
                int row = warp_m * 32 + i * 16 + (lane & 15);
                uint32_t off = swz(row, c0);
                LDSM4(ah[i][0], ah[i][1], ah[i][2], ah[i][3], st + STG_A_H + off);
                LDSM4(al[i][0], al[i][1], al[i][2], al[i][3], st + STG_A_L + off);
            }
            uint32_t bh[4][2], bl[4][2];
#pragma unroll
            for (int j2 = 0; j2 < 2; j2++) {
                int row = warp_n * 32 + j2 * 16 + (lane & 15);
                uint32_t off = swz(row, c0);
                uint32_t t0, t1, t2, t3;
                LDSM4(t0, t1, t2, t3, st + STG_B_H + off);
                bh[j2 * 2 + 0][0] = t0; bh[j2 * 2 + 1][0] = t1;
                bh[j2 * 2 + 0][1] = t2; bh[j2 * 2 + 1][1] = t3;
                LDSM4(t0, t1, t2, t3, st + STG_B_L + off);
                bl[j2 * 2 + 0][0] = t0; bl[j2 * 2 + 1][0] = t1;
                bl[j2 * 2 + 0][1] = t2; bl[j2 * 2 + 1][1] = t3;
            }
#pragma unroll
            for (int i = 0; i < 2; i++)
#pragma unroll
                for (int j = 0; j < 4; j++) {
                    MMA_BF16(acc[i][j], ah[i], bh[j]);
                    MMA_BF16(acc[i][j], ah[i], bl[j]);
                    MMA_BF16(acc[i][j], al[i], bh[j]);
                }
        }
        __syncthreads();
    }

#pragma unroll
    for (int i = 0; i < 2; i++) {
        int row0 = mBase + warp_m * 32 + i * 16 + (lane >> 2);
#pragma unroll
        for (int j = 0; j < 4; j++) {
            int col = nBase + warp_n * 32 + j * 8 + (lane & 3) * 2;
            if (row0 < M) {
                *reinterpret_cast<float2*>(&C[(size_t)row0 * Ncol + col]) =
                    make_float2(acc[i][j][0], acc[i][j][1]);
                if (C16)
                    *reinterpret_cast<__half2*>(&C16[(size_t)row0 * Ncol + col]) =
                        __floats2half2_rn(acc[i][j][0], acc[i][j][1]);
            }
            if (row0 + 8 < M) {
                *reinterpret_cast<float2*>(&C[(size_t)(row0 + 8) * Ncol + col]) =
                    make_float2(acc[i][j][2], acc[i][j][3]);
                if (C16)
                    *reinterpret_cast<__half2*>(&C16[(size_t)(row0 + 8) * Ncol + col]) =
                        __floats2half2_rn(acc[i][j][2], acc[i][j][3]);
            }
        }
    }
}

// ---------------- el/er coefficients ----------------
__global__ void attn_coef_kernel(const float* __restrict__ h,
                                 const float* __restrict__ al,
                                 const float* __restrict__ ar,
                                 float* __restrict__ el,
                                 float* __restrict__ er,
                                 int n, int heads, int dim) {
    int warpId = (blockIdx.x * blockDim.x + threadIdx.x) >> 5;
    int lane   = threadIdx.x & 31;
    int total  = n * heads;
    if (warpId >= total) return;
    int node = warpId / heads;
    int hd   = warpId - node * heads;
    const float* hp  = h + (size_t)node * heads * dim + (size_t)hd * dim;
    const float* alp = al + (size_t)hd * dim;
    const float* arp = ar + (size_t)hd * dim;
    float sl = 0.f, sr = 0.f;
    for (int c = lane * 4; c < dim; c += 128) {
        float4 hv = *reinterpret_cast<const float4*>(hp + c);
        float4 av = *reinterpret_cast<const float4*>(alp + c);
        float4 bv = *reinterpret_cast<const float4*>(arp + c);
        sl += hv.x * av.x + hv.y * av.y + hv.z * av.z + hv.w * av.w;
        sr += hv.x * bv.x + hv.y * bv.y + hv.z * bv.z + hv.w * bv.w;
    }
#pragma unroll
    for (int o = 16; o > 0; o >>= 1) {
        sl += __shfl_xor_sync(0xffffffffu, sl, o);
        sr += __shfl_xor_sync(0xffffffffu, sr, o);
    }
    if (lane == 0) { el[warpId] = sl; er[warpId] = sr; }
}

// ---------------- merged CSR build (both layers, blockIdx.y = layer) ----------------
__global__ void zero2_kernel(int* __restrict__ p, int n) {
    int i = blockIdx.x * blockDim.x + threadIdx.x;
    if (i < n) p[i] = 0;
}
__global__ void hist2_kernel(const int* __restrict__ dst1, const int* __restrict__ dst2,
                             int* __restrict__ cnt) {
    int i = blockIdx.x * blockDim.x + threadIdx.x;
    if (i >= NE) return;
    int layer = blockIdx.y;
    const int* d = layer ? dst2 : dst1;
    atomicAdd(&cnt[layer * NN + d[i]], 1);
}
__global__ __launch_bounds__(SCAN_BS)
void scan_part2_kernel(const int* __restrict__ cnt, int* __restrict__ part,
                       int* __restrict__ bsum) {
    __shared__ int sm[SCAN_BS];
    int layer = blockIdx.y;
    int tid = threadIdx.x;
    int gi = blockIdx.x * SCAN_BS + tid;
    int x = (gi < NN) ? cnt[layer * NN + gi] : 0;
    sm[tid] = x;
    __syncthreads();
#pragma unroll
    for (int off = 1; off < SCAN_BS; off <<= 1) {
        int v = (tid >= off) ? sm[tid - off] : 0;
        __syncthreads();
        sm[tid] += v;
        __syncthreads();
    }
    if (gi < NN) part[layer * NN + gi] = sm[tid] - x;
    if (tid == SCAN_BS - 1) bsum[layer * 64 + blockIdx.x] = sm[tid];
}
__global__ void scan_sums2_kernel(const int* __restrict__ bsum, int* __restrict__ soff) {
    __shared__ int sm[64];
    int layer = blockIdx.x;
    int tid = threadIdx.x;
    int x = (tid < SCAN_NB) ? bsum[layer * 64 + tid] : 0;
    sm[tid] = x;
    __syncthreads();
#pragma unroll
    for (int off = 1; off < 64; off <<= 1) {
        int v = (tid >= off) ? sm[tid - off] : 0;
        __syncthreads();
        sm[tid] += v;
        __syncthreads();
    }
    soff[layer * 64 + tid] = sm[tid] - x;
}
__global__ void finalize2_kernel(const int* __restrict__ part,
                                 const int* __restrict__ soff,
                                 int* __restrict__ rp1, int* __restrict__ rp2,
                                 int* __restrict__ cursor) {
    int i = blockIdx.x * blockDim.x + threadIdx.x;
    int layer = blockIdx.y;
    int* rp = layer ? rp2 : rp1;
    if (i < NN) {
        int v = part[layer * NN + i] + soff[layer * 64 + i / SCAN_BS];
        rp[i] = v;
        cursor[layer * NN + i] = v;
    }
    if (i == 0) rp[NN] = NE;
}
__global__ void fill2_kernel(const int* __restrict__ src1, const int* __restrict__ dst1,
                             const int* __restrict__ src2, const int* __restrict__ dst2,
                             int* __restrict__ cursor,
                             int* __restrict__ csrc1, int* __restrict__ csrc2) {
    int i = blockIdx.x * blockDim.x + threadIdx.x;
    if (i >= NE) return;
    int layer = blockIdx.y;
    const int* s = layer ? src2 : src1;
    const int* d = layer ? dst2 : dst1;
    int* c = layer ? csrc2 : csrc1;
    int pos = atomicAdd(&cursor[layer * NN + d[i]], 1);
    c[pos] = s[i];
}

// ---------------- fused softmax + aggregation: SINGLE edge sweep ----------------
// F16GATHER: message values gathered from an fp16 table (halves gather traffic).
template<int H, int D, int TPB, bool ELU, bool BF16OUT, bool F16GATHER>
__global__ __launch_bounds__(TPB)
void agg_kernel(const int* __restrict__ rowptr,
                const int* __restrict__ csrc,
                const float* __restrict__ hsrc,
                const __half* __restrict__ hsrc16,
                const float* __restrict__ el,
                const float* __restrict__ er,
                float* __restrict__ outp,
                __nv_bfloat16* __restrict__ ohi,
                __nv_bfloat16* __restrict__ olo) {
    const int n   = blockIdx.x;
    const int tid = threadIdx.x;

    const int base = rowptr[n];
    const int deg  = rowptr[n + 1] - base;

    const int col  = tid * 4;
    const int head = col / D;                    // warp-uniform
    const float er_h = er[(size_t)n * H + head]; // warp-broadcast load

    float s = 0.f;
    float4 acc = make_float4(0.f, 0.f, 0.f, 0.f);

    int sn = (deg > 0) ? csrc[base] : 0;
    for (int j = 0; j < deg; j++) {
        int sn_next = (j + 1 < deg) ? csrc[base + j + 1] : 0;
        float x = el[(size_t)sn * H + head] + er_h;
        float e = x >= 0.f ? x : NEG_SLOPE * x;
        float ee = __expf(e);
        s += ee;
        if constexpr (F16GATHER) {
            uint2 raw = *reinterpret_cast<const uint2*>(&hsrc16[(size_t)sn * (H * D) + col]);
            float2 f0 = __half22float2(*reinterpret_cast<__half2*>(&raw.x));
            float2 f1 = __half22float2(*reinterpret_cast<__half2*>(&raw.y));
            acc.x += f0.x * ee;
            acc.y += f0.y * ee;
            acc.z += f1.x * ee;
            acc.w += f1.y * ee;
        } else {
            float4 v = *reinterpret_cast<const float4*>(&hsrc[(size_t)sn * (H * D) + col]);
            acc.x += v.x * ee;
            acc.y += v.y * ee;
            acc.z += v.z * ee;
            acc.w += v.w * ee;
        }
        sn = sn_next;
    }

    float inv = 1.f / (s + 1e-9f);
    acc.x *= inv; acc.y *= inv; acc.z *= inv; acc.w *= inv;

    if (ELU) {
        acc.x = acc.x > 0.f ? acc.x : expm1f(acc.x);
        acc.y = acc.y > 0.f ? acc.y : expm1f(acc.y);
        acc.z = acc.z > 0.f ? acc.z : expm1f(acc.z);
        acc.w = acc.w > 0.f ? acc.w : expm1f(acc.w);
    }

    if constexpr (BF16OUT) {
        __nv_bfloat16 hx, hy, hz, hw, lx, ly, lz, lw;
        split1(acc.x, hx, lx); split1(acc.y, hy, ly);
        split1(acc.z, hz, lz); split1(acc.w, hw, lw);
        uint2 Hp, Lp;
        Hp.x = pk(hx, hy); Hp.y = pk(hz, hw);
        Lp.x = pk(lx, ly); Lp.y = pk(lz, lw);
        *reinterpret_cast<uint2*>(&ohi[(size_t)n * (H * D) + col]) = Hp;
        *reinterpret_cast<uint2*>(&olo[(size_t)n * (H * D) + col]) = Lp;
    } else {
        *reinterpret_cast<float4*>(&outp[(size_t)n * (H * D) + col]) = acc;
    }
}

// ---------------- launch ----------------
extern "C" void kernel_launch(void* const* d_in, const int* in_sizes, int n_in,
                              void* d_out, int out_size) {
    const float* feat = (const float*)d_in[0];
    const int*   src1 = (const int*)d_in[1];
    const int*   dst1 = (const int*)d_in[2];
    const int*   src2 = (const int*)d_in[3];
    const int*   dst2 = (const int*)d_in[4];
    const float* W1   = (const float*)d_in[5];
    const float* al1  = (const float*)d_in[6];
    const float* ar1  = (const float*)d_in[7];
    const float* W2   = (const float*)d_in[8];
    const float* al2  = (const float*)d_in[9];
    const float* ar2  = (const float*)d_in[10];
    float* outp = (float*)d_out;

    float *h1, *h2, *el1, *er1, *el2, *er2;
    __half *h1f16;
    __nv_bfloat16 *a1hi, *a1lo, *a2hi, *a2lo, *w1thi, *w1tlo, *w2thi, *w2tlo;
    int *cnt, *part, *bsum, *soff, *cursor, *rp1, *rp2, *csrc1, *csrc2;
    cudaGetSymbolAddress((void**)&h1,    g_h1);
    cudaGetSymbolAddress((void**)&h1f16, g_h1f16);
    cudaGetSymbolAddress((void**)&h2,    g_h2);
    cudaGetSymbolAddress((void**)&a1hi, g_a1hi);
    cudaGetSymbolAddress((void**)&a1lo, g_a1lo);
    cudaGetSymbolAddress((void**)&a2hi, g_a2hi);
    cudaGetSymbolAddress((void**)&a2lo, g_a2lo);
    cudaGetSymbolAddress((void**)&w1thi, g_w1thi);
    cudaGetSymbolAddress((void**)&w1tlo, g_w1tlo);
    cudaGetSymbolAddress((void**)&w2thi, g_w2thi);
    cudaGetSymbolAddress((void**)&w2tlo, g_w2tlo);
    cudaGetSymbolAddress((void**)&el1,  g_el1);
    cudaGetSymbolAddress((void**)&er1,  g_er1);
    cudaGetSymbolAddress((void**)&el2,  g_el2);
    cudaGetSymbolAddress((void**)&er2,  g_er2);
    cudaGetSymbolAddress((void**)&cnt,    g_cnt);
    cudaGetSymbolAddress((void**)&part,   g_part);
    cudaGetSymbolAddress((void**)&bsum,   g_bsum);
    cudaGetSymbolAddress((void**)&soff,   g_soff);
    cudaGetSymbolAddress((void**)&cursor, g_cursor);
    cudaGetSymbolAddress((void**)&rp1,    g_rowptr1);
    cudaGetSymbolAddress((void**)&rp2,    g_rowptr2);
    cudaGetSymbolAddress((void**)&csrc1,  g_csrc1);
    cudaGetSymbolAddress((void**)&csrc2,  g_csrc2);

    const int TB = 256;
    const int edgeBlocks = (NE + TB - 1) / TB;

    // ---------- prep: splits + both CSR builds ----------
    split_kernel<<<2048, TB>>>((const float4*)feat, (uint2*)a1hi, (uint2*)a1lo,
                               NN * IN_DIM / 4);
    tsplit_kernel<<<(C1N * IN_DIM + TB - 1) / TB, TB>>>(W1, w1thi, w1tlo, IN_DIM, C1N);
    tsplit_kernel<<<(C2N * C1N + TB - 1) / TB, TB>>>(W2, w2thi, w2tlo, C1N, C2N);

    zero2_kernel<<<(2 * NN + TB - 1) / TB, TB>>>(cnt, 2 * NN);
    hist2_kernel<<<dim3(edgeBlocks, 2), TB>>>(dst1, dst2, cnt);
    scan_part2_kernel<<<dim3(SCAN_NB, 2), SCAN_BS>>>(cnt, part, bsum);
    scan_sums2_kernel<<<2, 64>>>(bsum, soff);
    finalize2_kernel<<<dim3((NN + TB - 1) / TB, 2), TB>>>(part, soff, rp1, rp2, cursor);
    fill2_kernel<<<dim3(edgeBlocks, 2), TB>>>(src1, dst1, src2, dst2, cursor, csrc1, csrc2);

    // ---------- layer 1 ----------
    mma_bf16x3_kernel<<<dim3(C1N / 64, (NN + 127) / 128), 256>>>(
        NN, C1N, IN_DIM, a1hi, a1lo, w1thi, w1tlo, h1, h1f16);
    attn_coef_kernel<<<(NN * H1N * 32 + TB - 1) / TB, TB>>>(h1, al1, ar1, el1, er1, NN, H1N, D1N);
    agg_kernel<H1N, D1N, 128, true, true, true><<<NN, 128>>>(
        rp1, csrc1, h1, h1f16, el1, er1, nullptr, a2hi, a2lo);

    // ---------- layer 2 ----------
    mma_bf16x3_kernel<<<dim3(C2N / 64, (NN + 127) / 128), 256>>>(
        NN, C2N, C1N, a2hi, a2lo, w2thi, w2tlo, h2, nullptr);
    attn_coef_kernel<<<(NN * H2N * 32 + TB - 1) / TB, TB>>>(h2, al2, ar2, el2, er2, NN, H2N, D2N);
    agg_kernel<H2N, D2N, 64, false, false, false><<<NN, 64>>>(
        rp2, csrc2, h2, nullptr, el2, er2, outp, nullptr, nullptr);
}

// round 15
// speedup vs baseline: 1.0605x; 1.0605x over previous
#include <cuda_runtime.h>
#include <cuda_bf16.h>
#include <math.h>
#include <stdint.h>

// ---------------- problem constants ----------------
#define NN      50000
#define NE      800000
#define IN_DIM  256
#define H1N     4
#define D1N     128
#define C1N     512
#define H2N     1
#define D2N     256
#define C2N     256
#define NEG_SLOPE 0.2f

#define SCAN_BS 1024
#define SCAN_NB ((NN + SCAN_BS - 1) / SCAN_BS)

// ---------------- device scratch ----------------
__device__ float                         g_h1 [(size_t)NN * C1N];
__device__ float                         g_h2 [(size_t)NN * C2N];
__device__ __align__(16) __nv_bfloat16   g_a1hi[(size_t)NN * IN_DIM];
__device__ __align__(16) __nv_bfloat16   g_a1lo[(size_t)NN * IN_DIM];
__device__ __align__(16) __nv_bfloat16   g_a2hi[(size_t)NN * C1N];
__device__ __align__(16) __nv_bfloat16   g_a2lo[(size_t)NN * C1N];
__device__ __align__(16) __nv_bfloat16   g_w1thi[(size_t)C1N * IN_DIM];
__device__ __align__(16) __nv_bfloat16   g_w1tlo[(size_t)C1N * IN_DIM];
__device__ __align__(16) __nv_bfloat16   g_w2thi[(size_t)C2N * C1N];
__device__ __align__(16) __nv_bfloat16   g_w2tlo[(size_t)C2N * C1N];
__device__ float                         g_el1[(size_t)NN * H1N];
__device__ float                         g_er1[(size_t)NN * H1N];
__device__ float                         g_el2[(size_t)NN * H2N];
__device__ float                         g_er2[(size_t)NN * H2N];
// merged CSR scratch (layer-major)
__device__ int   g_cnt[2 * NN];
__device__ int   g_part[2 * NN];
__device__ int   g_bsum[128];
__device__ int   g_soff[128];
__device__ int   g_cursor[2 * NN];
__device__ int   g_rowptr1[NN + 1];
__device__ int   g_rowptr2[NN + 1];
__device__ int   g_csrc1[NE];
__device__ int   g_csrc2[NE];

// ---------------- bf16 split helpers ----------------
__device__ __forceinline__ unsigned pk(__nv_bfloat16 a, __nv_bfloat16 b) {
    __nv_bfloat162 t = __halves2bfloat162(a, b);
    return *reinterpret_cast<unsigned*>(&t);
}
__device__ __forceinline__ void split1(float x, __nv_bfloat16& h, __nv_bfloat16& l) {
    h = __float2bfloat16(x);
    l = __float2bfloat16(x - __bfloat162float(h));
}

// ---------------- prep kernels ----------------
__global__ void split_kernel(const float4* __restrict__ x,
                             uint2* __restrict__ hi, uint2* __restrict__ lo, int n4) {
    int stride = gridDim.x * blockDim.x;
    for (int i = blockIdx.x * blockDim.x + threadIdx.x; i < n4; i += stride) {
        float4 v = x[i];
        __nv_bfloat16 hx, hy, hz, hw, lx, ly, lz, lw;
        split1(v.x, hx, lx); split1(v.y, hy, ly);
        split1(v.z, hz, lz); split1(v.w, hw, lw);
        uint2 H, L;
        H.x = pk(hx, hy); H.y = pk(hz, hw);
        L.x = pk(lx, ly); L.y = pk(lz, lw);
        hi[i] = H; lo[i] = L;
    }
}

__global__ void tsplit_kernel(const float* __restrict__ W,
                              __nv_bfloat16* __restrict__ thi,
                              __nv_bfloat16* __restrict__ tlo, int K, int Ncol) {
    int idx = blockIdx.x * blockDim.x + threadIdx.x;
    if (idx >= K * Ncol) return;
    int n = idx / K, k = idx - n * K;
    float x = W[(size_t)k * Ncol + n];
    __nv_bfloat16 h, l;
    split1(x, h, l);
    thi[idx] = h; tlo[idx] = l;
}

// ---------------- mma.sync bf16x3 GEMM (proven R10 config) ----------------
#define MMA_BF16(D, A, B)                                                        \
    asm volatile("mma.sync.aligned.m16n8k16.row.col.f32.bf16.bf16.f32 "          \
                 "{%0,%1,%2,%3},{%4,%5,%6,%7},{%8,%9},{%0,%1,%2,%3};"            \
                 : "+f"((D)[0]), "+f"((D)[1]), "+f"((D)[2]), "+f"((D)[3])        \
                 : "r"((A)[0]), "r"((A)[1]), "r"((A)[2]), "r"((A)[3]),           \
                   "r"((B)[0]), "r"((B)[1]))

#define LDSM4(R0, R1, R2, R3, ADDR)                                              \
    asm volatile("ldmatrix.sync.aligned.m8n8.x4.shared.b16 {%0,%1,%2,%3}, [%4];" \
                 : "=r"(R0), "=r"(R1), "=r"(R2), "=r"(R3) : "r"(ADDR))

__device__ __forceinline__ void cp16(uint32_t saddr, const void* gaddr, bool pred) {
    int sz = pred ? 16 : 0;
    asm volatile("cp.async.cg.shared.global [%0], [%1], 16, %2;"
                 :: "r"(saddr), "l"(gaddr), "r"(sz));
}
#define CP_COMMIT() asm volatile("cp.async.commit_group;")
template<int N>
__device__ __forceinline__ void cp_wait() {
    asm volatile("cp.async.wait_group %0;" :: "n"(N));
}

__device__ __forceinline__ uint32_t swz(int r, int c) {
    return (uint32_t)((r * 4 + (c ^ (r & 3))) << 4);
}

#define STG_A_H 0
#define STG_A_L 8192
#define STG_B_H 16384
#define STG_B_L 20480
#define STG_SZ  24576

__global__ __launch_bounds__(256, 3)
void mma_bf16x3_kernel(int M, int Ncol, int K,
                       const __nv_bfloat16* __restrict__ Ahi,
                       const __nv_bfloat16* __restrict__ Alo,
                       const __nv_bfloat16* __restrict__ Bthi,
                       const __nv_bfloat16* __restrict__ Btlo,
                       float* __restrict__ C) {
    __shared__ char smem[2 * STG_SZ];
    const int tid  = threadIdx.x;
    const int lane = tid & 31;
    const int wid  = tid >> 5;
    const int warp_m = wid & 3;
    const int warp_n = wid >> 2;
    const int mBase = blockIdx.y * 128;
    const int nBase = blockIdx.x * 64;
    const uint32_t sb = (uint32_t)__cvta_generic_to_shared(smem);

    float acc[2][4][4];
#pragma unroll
    for (int i = 0; i < 2; i++)
#pragma unroll
        for (int j = 0; j < 4; j++)
#pragma unroll
            for (int c = 0; c < 4; c++) acc[i][j][c] = 0.f;

    const int ar = tid >> 2;
    const int ac = tid & 3;
    const uint32_t soA0 = swz(ar, ac);
    const uint32_t soA1 = swz(ar + 64, ac);

    const int nk = K >> 5;

    auto load_stage = [&](int kb, int s) {
        const uint32_t st = sb + (uint32_t)s * STG_SZ;
        const int kOff = kb * 32 + ac * 8;
        {
            bool p0 = (mBase + ar) < M;
            bool p1 = (mBase + ar + 64) < M;
            size_t o0 = (size_t)(mBase + ar) * K + kOff;
            size_t o1 = (size_t)(mBase + ar + 64) * K + kOff;
            cp16(st + STG_A_H + soA0, Ahi + o0, p0);
            cp16(st + STG_A_H + soA1, Ahi + o1, p1);
            cp16(st + STG_A_L + soA0, Alo + o0, p0);
            cp16(st + STG_A_L + soA1, Alo + o1, p1);
        }
        {
            size_t ob = (size_t)(nBase + ar) * K + kOff;
            cp16(st + STG_B_H + soA0, Bthi + ob, true);
            cp16(st + STG_B_L + soA0, Btlo + ob, true);
        }
        CP_COMMIT();
    };

    load_stage(0, 0);

    for (int kb = 0; kb < nk; kb++) {
        if (kb + 1 < nk) load_stage(kb + 1, (kb + 1) & 1);
        if (kb + 1 < nk) cp_wait<1>(); else cp_wait<0>();
        __syncthreads();

        const uint32_t st = sb + (uint32_t)(kb & 1) * STG_SZ;
#pragma unroll
        for (int ks = 0; ks < 2; ks++) {
            const int c0 = ks * 2 + (lane >> 4);
            uint32_t ah[2][4], al[2][4];
#pragma unroll
            for (int i = 0; i < 2; i++) {
                int row = warp_m * 32 + i * 16 + (lane & 15);
                uint32_t off = swz(row, c0);
                LDSM4(ah[i][0], ah[i][1], ah[i][2], ah[i][3], st + STG_A_H + off);
                LDSM4(al[i][0], al[i][1], al[i][2], al[i][3], st + STG_A_L + off);
            }
            uint32_t bh[4][2], bl[4][2];
#pragma unroll
            for (int j2 = 0; j2 < 2; j2++) {
                int row = warp_n * 32 + j2 * 16 + (lane & 15);
                uint32_t off = swz(row, c0);
                uint32_t t0, t1, t2, t3;
                LDSM4(t0, t1, t2, t3, st + STG_B_H + off);
                bh[j2 * 2 + 0][0] = t0; bh[j2 * 2 + 1][0] = t1;
                bh[j2 * 2 + 0][1] = t2; bh[j2 * 2 + 1][1] = t3;
                LDSM4(t0, t1, t2, t3, st + STG_B_L + off);
                bl[j2 * 2 + 0][0] = t0; bl[j2 * 2 + 1][0] = t1;
                bl[j2 * 2 + 0][1] = t2; bl[j2 * 2 + 1][1] = t3;
            }
#pragma unroll
            for (int i = 0; i < 2; i++)
#pragma unroll
                for (int j = 0; j < 4; j++) {
                    MMA_BF16(acc[i][j], ah[i], bh[j]);
                    MMA_BF16(acc[i][j], ah[i], bl[j]);
                    MMA_BF16(acc[i][j], al[i], bh[j]);
                }
        }
        __syncthreads();
    }

#pragma unroll
    for (int i = 0; i < 2; i++) {
        int row0 = mBase + warp_m * 32 + i * 16 + (lane >> 2);
#pragma unroll
        for (int j = 0; j < 4; j++) {
            int col = nBase + warp_n * 32 + j * 8 + (lane & 3) * 2;
            if (row0 < M)
                *reinterpret_cast<float2*>(&C[(size_t)row0 * Ncol + col]) =
                    make_float2(acc[i][j][0], acc[i][j][1]);
            if (row0 + 8 < M)
                *reinterpret_cast<float2*>(&C[(size_t)(row0 + 8) * Ncol + col]) =
                    make_float2(acc[i][j][2], acc[i][j][3]);
        }
    }
}

// ---------------- el/er coefficients ----------------
__global__ void attn_coef_kernel(const float* __restrict__ h,
                                 const float* __restrict__ al,
                                 const float* __restrict__ ar,
                                 float* __restrict__ el,
                                 float* __restrict__ er,
                                 int n, int heads, int dim) {
    int warpId = (blockIdx.x * blockDim.x + threadIdx.x) >> 5;
    int lane   = threadIdx.x & 31;
    int total  = n * heads;
    if (warpId >= total) return;
    int node = warpId / heads;
    int hd   = warpId - node * heads;
    const float* hp  = h + (size_t)node * heads * dim + (size_t)hd * dim;
    const float* alp = al + (size_t)hd * dim;
    const float* arp = ar + (size_t)hd * dim;
    float sl = 0.f, sr = 0.f;
    for (int c = lane * 4; c < dim; c += 128) {
        float4 hv = *reinterpret_cast<const float4*>(hp + c);
        float4 av = *reinterpret_cast<const float4*>(alp + c);
        float4 bv = *reinterpret_cast<const float4*>(arp + c);
        sl += hv.x * av.x + hv.y * av.y + hv.z * av.z + hv.w * av.w;
        sr += hv.x * bv.x + hv.y * bv.y + hv.z * bv.z + hv.w * bv.w;
    }
#pragma unroll
    for (int o = 16; o > 0; o >>= 1) {
        sl += __shfl_xor_sync(0xffffffffu, sl, o);
        sr += __shfl_xor_sync(0xffffffffu, sr, o);
    }
    if (lane == 0) { el[warpId] = sl; er[warpId] = sr; }
}

// ---------------- merged CSR build (both layers, blockIdx.y = layer) ----------------
__global__ void zero2_kernel(int* __restrict__ p, int n) {
    int i = blockIdx.x * blockDim.x + threadIdx.x;
    if (i < n) p[i] = 0;
}
__global__ void hist2_kernel(const int* __restrict__ dst1, const int* __restrict__ dst2,
                             int* __restrict__ cnt) {
    int i = blockIdx.x * blockDim.x + threadIdx.x;
    if (i >= NE) return;
    int layer = blockIdx.y;
    const int* d = layer ? dst2 : dst1;
    atomicAdd(&cnt[layer * NN + d[i]], 1);
}
__global__ __launch_bounds__(SCAN_BS)
void scan_part2_kernel(const int* __restrict__ cnt, int* __restrict__ part,
                       int* __restrict__ bsum) {
    __shared__ int sm[SCAN_BS];
    int layer = blockIdx.y;
    int tid = threadIdx.x;
    int gi = blockIdx.x * SCAN_BS + tid;
    int x = (gi < NN) ? cnt[layer * NN + gi] : 0;
    sm[tid] = x;
    __syncthreads();
#pragma unroll
    for (int off = 1; off < SCAN_BS; off <<= 1) {
        int v = (tid >= off) ? sm[tid - off] : 0;
        __syncthreads();
        sm[tid] += v;
        __syncthreads();
    }
    if (gi < NN) part[layer * NN + gi] = sm[tid] - x;
    if (tid == SCAN_BS - 1) bsum[layer * 64 + blockIdx.x] = sm[tid];
}
__global__ void scan_sums2_kernel(const int* __restrict__ bsum, int* __restrict__ soff) {
    __shared__ int sm[64];
    int layer = blockIdx.x;
    int tid = threadIdx.x;
    int x = (tid < SCAN_NB) ? bsum[layer * 64 + tid] : 0;
    sm[tid] = x;
    __syncthreads();
#pragma unroll
    for (int off = 1; off < 64; off <<= 1) {
        int v = (tid >= off) ? sm[tid - off] : 0;
        __syncthreads();
        sm[tid] += v;
        __syncthreads();
    }
    soff[layer * 64 + tid] = sm[tid] - x;
}
__global__ void finalize2_kernel(const int* __restrict__ part,
                                 const int* __restrict__ soff,
                                 int* __restrict__ rp1, int* __restrict__ rp2,
                                 int* __restrict__ cursor) {
    int i = blockIdx.x * blockDim.x + threadIdx.x;
    int layer = blockIdx.y;
    int* rp = layer ? rp2 : rp1;
    if (i < NN) {
        int v = part[layer * NN + i] + soff[layer * 64 + i / SCAN_BS];
        rp[i] = v;
        cursor[layer * NN + i] = v;
    }
    if (i == 0) rp[NN] = NE;
}
__global__ void fill2_kernel(const int* __restrict__ src1, const int* __restrict__ dst1,
                             const int* __restrict__ src2, const int* __restrict__ dst2,
                             int* __restrict__ cursor,
                             int* __restrict__ csrc1, int* __restrict__ csrc2) {
    int i = blockIdx.x * blockDim.x + threadIdx.x;
    if (i >= NE) return;
    int layer = blockIdx.y;
    const int* s = layer ? src2 : src1;
    const int* d = layer ? dst2 : dst1;
    int* c = layer ? csrc2 : csrc1;
    int pos = atomicAdd(&cursor[layer * NN + d[i]], 1);
    c[pos] = s[i];
}

// ---------------- fused softmax + aggregation: single sweep, 4-way unrolled ----------------
template<int H, int D, int TPB, bool ELU, bool BF16OUT>
__global__ __launch_bounds__(TPB)
void agg_kernel(const int* __restrict__ rowptr,
                const int* __restrict__ csrc,
                const float* __restrict__ hsrc,
                const float* __restrict__ el,
                const float* __restrict__ er,
                float* __restrict__ outp,
                __nv_bfloat16* __restrict__ ohi,
                __nv_bfloat16* __restrict__ olo) {
    const int n   = blockIdx.x;
    const int tid = threadIdx.x;

    const int base = rowptr[n];
    const int deg  = rowptr[n + 1] - base;

    const int col  = tid * 4;
    const int head = col / D;                    // warp-uniform
    const float er_h = er[(size_t)n * H + head]; // warp-broadcast

    float s = 0.f;
    float4 acc = make_float4(0.f, 0.f, 0.f, 0.f);

    int j = 0;
    // 4-way unrolled main loop: batch the index, el and row loads (MLP=4)
    for (; j + 4 <= deg; j += 4) {
        int s0 = csrc[base + j + 0];
        int s1 = csrc[base + j + 1];
        int s2 = csrc[base + j + 2];
        int s3 = csrc[base + j + 3];
        float x0 = el[(size_t)s0 * H + head];
        float x1 = el[(size_t)s1 * H + head];
        float x2 = el[(size_t)s2 * H + head];
        float x3 = el[(size_t)s3 * H + head];
        float4 v0 = *reinterpret_cast<const float4*>(&hsrc[(size_t)s0 * (H * D) + col]);
        float4 v1 = *reinterpret_cast<const float4*>(&hsrc[(size_t)s1 * (H * D) + col]);
        float4 v2 = *reinterpret_cast<const float4*>(&hsrc[(size_t)s2 * (H * D) + col]);
        float4 v3 = *reinterpret_cast<const float4*>(&hsrc[(size_t)s3 * (H * D) + col]);
        x0 += er_h; x1 += er_h; x2 += er_h; x3 += er_h;
        float e0 = x0 >= 0.f ? x0 : NEG_SLOPE * x0;
        float e1 = x1 >= 0.f ? x1 : NEG_SLOPE * x1;
        float e2 = x2 >= 0.f ? x2 : NEG_SLOPE * x2;
        float e3 = x3 >= 0.f ? x3 : NEG_SLOPE * x3;
        float ee0 = __expf(e0), ee1 = __expf(e1), ee2 = __expf(e2), ee3 = __expf(e3);
        s += (ee0 + ee1) + (ee2 + ee3);
        acc.x += v0.x * ee0 + v1.x * ee1 + v2.x * ee2 + v3.x * ee3;
        acc.y += v0.y * ee0 + v1.y * ee1 + v2.y * ee2 + v3.y * ee3;
        acc.z += v0.z * ee0 + v1.z * ee1 + v2.z * ee2 + v3.z * ee3;
        acc.w += v0.w * ee0 + v1.w * ee1 + v2.w * ee2 + v3.w * ee3;
    }
    // tail
    for (; j < deg; j++) {
        int sn = csrc[base + j];
        float x = el[(size_t)sn * H + head] + er_h;
        float e = x >= 0.f ? x : NEG_SLOPE * x;
        float ee = __expf(e);
        s += ee;
        float4 v = *reinterpret_cast<const float4*>(&hsrc[(size_t)sn * (H * D) + col]);
        acc.x += v.x * ee;
        acc.y += v.y * ee;
        acc.z += v.z * ee;
        acc.w += v.w * ee;
    }

    float inv = 1.f / (s + 1e-9f);
    acc.x *= inv; acc.y *= inv; acc.z *= inv; acc.w *= inv;

    if (ELU) {
        acc.x = acc.x > 0.f ? acc.x : expm1f(acc.x);
        acc.y = acc.y > 0.f ? acc.y : expm1f(acc.y);
        acc.z = acc.z > 0.f ? acc.z : expm1f(acc.z);
        acc.w = acc.w > 0.f ? acc.w : expm1f(acc.w);
    }

    if constexpr (BF16OUT) {
        __nv_bfloat16 hx, hy, hz, hw, lx, ly, lz, lw;
        split1(acc.x, hx, lx); split1(acc.y, hy, ly);
        split1(acc.z, hz, lz); split1(acc.w, hw, lw);
        uint2 Hp, Lp;
        Hp.x = pk(hx, hy); Hp.y = pk(hz, hw);
        Lp.x = pk(lx, ly); Lp.y = pk(lz, lw);
        *reinterpret_cast<uint2*>(&ohi[(size_t)n * (H * D) + col]) = Hp;
        *reinterpret_cast<uint2*>(&olo[(size_t)n * (H * D) + col]) = Lp;
    } else {
        *reinterpret_cast<float4*>(&outp[(size_t)n * (H * D) + col]) = acc;
    }
}

// ---------------- launch ----------------
extern "C" void kernel_launch(void* const* d_in, const int* in_sizes, int n_in,
                              void* d_out, int out_size) {
    const float* feat = (const float*)d_in[0];
    const int*   src1 = (const int*)d_in[1];
    const int*   dst1 = (const int*)d_in[2];
    const int*   src2 = (const int*)d_in[3];
    const int*   dst2 = (const int*)d_in[4];
    const float* W1   = (const float*)d_in[5];
    const float* al1  = (const float*)d_in[6];
    const float* ar1  = (const float*)d_in[7];
    const float* W2   = (const float*)d_in[8];
    const float* al2  = (const float*)d_in[9];
    const float* ar2  = (const float*)d_in[10];
    float* outp = (float*)d_out;

    float *h1, *h2, *el1, *er1, *el2, *er2;
    __nv_bfloat16 *a1hi, *a1lo, *a2hi, *a2lo, *w1thi, *w1tlo, *w2thi, *w2tlo;
    int *cnt, *part, *bsum, *soff, *cursor, *rp1, *rp2, *csrc1, *csrc2;
    cudaGetSymbolAddress((void**)&h1,   g_h1);
    cudaGetSymbolAddress((void**)&h2,   g_h2);
    cudaGetSymbolAddress((void**)&a1hi, g_a1hi);
    cudaGetSymbolAddress((void**)&a1lo, g_a1lo);
    cudaGetSymbolAddress((void**)&a2hi, g_a2hi);
    cudaGetSymbolAddress((void**)&a2lo, g_a2lo);
    cudaGetSymbolAddress((void**)&w1thi, g_w1thi);
    cudaGetSymbolAddress((void**)&w1tlo, g_w1tlo);
    cudaGetSymbolAddress((void**)&w2thi, g_w2thi);
    cudaGetSymbolAddress((void**)&w2tlo, g_w2tlo);
    cudaGetSymbolAddress((void**)&el1,  g_el1);
    cudaGetSymbolAddress((void**)&er1,  g_er1);
    cudaGetSymbolAddress((void**)&el2,  g_el2);
    cudaGetSymbolAddress((void**)&er2,  g_er2);
    cudaGetSymbolAddress((void**)&cnt,    g_cnt);
    cudaGetSymbolAddress((void**)&part,   g_part);
    cudaGetSymbolAddress((void**)&bsum,   g_bsum);
    cudaGetSymbolAddress((void**)&soff,   g_soff);
    cudaGetSymbolAddress((void**)&cursor, g_cursor);
    cudaGetSymbolAddress((void**)&rp1,    g_rowptr1);
    cudaGetSymbolAddress((void**)&rp2,    g_rowptr2);
    cudaGetSymbolAddress((void**)&csrc1,  g_csrc1);
    cudaGetSymbolAddress((void**)&csrc2,  g_csrc2);

    const int TB = 256;
    const int edgeBlocks = (NE + TB - 1) / TB;

    // ---------- prep: splits + both CSR builds ----------
    split_kernel<<<2048, TB>>>((const float4*)feat, (uint2*)a1hi, (uint2*)a1lo,
                               NN * IN_DIM / 4);
    tsplit_kernel<<<(C1N * IN_DIM + TB - 1) / TB, TB>>>(W1, w1thi, w1tlo, IN_DIM, C1N);
    tsplit_kernel<<<(C2N * C1N + TB - 1) / TB, TB>>>(W2, w2thi, w2tlo, C1N, C2N);

    zero2_kernel<<<(2 * NN + TB - 1) / TB, TB>>>(cnt, 2 * NN);
    hist2_kernel<<<dim3(edgeBlocks, 2), TB>>>(dst1, dst2, cnt);
    scan_part2_kernel<<<dim3(SCAN_NB, 2), SCAN_BS>>>(cnt, part, bsum);
    scan_sums2_kernel<<<2, 64>>>(bsum, soff);
    finalize2_kernel<<<dim3((NN + TB - 1) / TB, 2), TB>>>(part, soff, rp1, rp2, cursor);
    fill2_kernel<<<dim3(edgeBlocks, 2), TB>>>(src1, dst1, src2, dst2, cursor, csrc1, csrc2);

    // ---------- layer 1 ----------
    mma_bf16x3_kernel<<<dim3(C1N / 64, (NN + 127) / 128), 256>>>(
        NN, C1N, IN_DIM, a1hi, a1lo, w1thi, w1tlo, h1);
    attn_coef_kernel<<<(NN * H1N * 32 + TB - 1) / TB, TB>>>(h1, al1, ar1, el1, er1, NN, H1N, D1N);
    agg_kernel<H1N, D1N, 128, true, true><<<NN, 128>>>(
        rp1, csrc1, h1, el1, er1, nullptr, a2hi, a2lo);

    // ---------- layer 2 ----------
    mma_bf16x3_kernel<<<dim3(C2N / 64, (NN + 127) / 128), 256>>>(
        NN, C2N, C1N, a2hi, a2lo, w2thi, w2tlo, h2);
    attn_coef_kernel<<<(NN * H2N * 32 + TB - 1) / TB, TB>>>(h2, al2, ar2, el2, er2, NN, H2N, D2N);
    agg_kernel<H2N, D2N, 64, false, false><<<NN, 64>>>(
        rp2, csrc2, h2, el2, er2, outp, nullptr, nullptr);
}